// round 13
// baseline (speedup 1.0000x reference)
#include <cuda_runtime.h>
#include <cuda_fp16.h>
#include <math.h>
#include <stdint.h>

// Problem constants
#define BB 32
#define TT 32
#define AD 32
#define HID 1536
#define K2 (2*HID)   // 3072

// Scratch (__device__ globals)
__device__ __half g_xf[BB*TT*K2];          // concat([a_emb, tau]) fp16
__device__ __half g_hf[BB*TT*HID];         // swish hidden fp16
__device__ float  g_part[2*BB*TT*HID];     // split-K partials (12.6 MB)
__device__ int g_gcat[32];
__device__ int g_gsamp[32][2];
__device__ int g_ngroups;

// ---------------------------------------------------------------------------
// Setup: group samples by cat in pairs. One warp.
// ---------------------------------------------------------------------------
__global__ void setup_groups(const int* __restrict__ cats)
{
    __shared__ int sc[32];
    int t = threadIdx.x;
    sc[t] = cats[t];
    __syncwarp();

    unsigned mask = 0;
    #pragma unroll
    for (int s = 0; s < 32; s++)
        if (sc[s] == t) mask |= (1u << s);
    int cnt = __popc(mask);
    int ng  = (cnt + 1) >> 1;

    int incl = ng;
    #pragma unroll
    for (int off = 1; off < 32; off <<= 1) {
        int v = __shfl_up_sync(0xffffffffu, incl, off);
        if (t >= off) incl += v;
    }
    int pre   = incl - ng;
    int total = __shfl_sync(0xffffffffu, incl, 31);
    if (t == 0) g_ngroups = total;

    unsigned m = mask;
    for (int g = 0; g < ng; g++) {
        int slot = pre + g;
        g_gcat[slot] = t;
        #pragma unroll
        for (int j = 0; j < 2; j++) {
            int s = -1;
            if (m) { s = __ffs(m) - 1; m &= m - 1; }
            g_gsamp[slot][j] = s;
        }
    }
    for (int slot = total + t; slot < 32; slot += 32) {
        g_gcat[slot] = -1;
        g_gsamp[slot][0] = -1;
        g_gsamp[slot][1] = -1;
    }
}

// ---------------------------------------------------------------------------
// Kernel 1: x = [actions @ W1[cat] + b1, sinusoidal(ts)] -> fp16
// ---------------------------------------------------------------------------
__global__ __launch_bounds__(256) void embed_kernel(
    const float* __restrict__ actions,
    const int*   __restrict__ timesteps,
    const int*   __restrict__ cats,
    const float* __restrict__ W1,
    const float* __restrict__ b1)
{
    int b = blockIdx.x;
    int p = blockIdx.y * 256 + threadIdx.x;
    int j = 2 * p;

    __shared__ float sa[TT*AD];
    for (int i = threadIdx.x; i < TT*AD; i += 256)
        sa[i] = actions[(size_t)b*TT*AD + i];
    __syncthreads();

    int cat = cats[b];
    const float* Wc = W1 + (size_t)cat * AD * HID;
    float2 bb = *reinterpret_cast<const float2*>(&b1[(size_t)cat*HID + j]);

    float2 wv[AD];
    #pragma unroll
    for (int k = 0; k < AD; k++)
        wv[k] = *reinterpret_cast<const float2*>(&Wc[(size_t)k*HID + j]);

    const float C = -9.210340371976184f / 768.0f;
    float ts = (float)timesteps[b];
    float freq = expf(C * (float)p);
    float s, c;
    sincosf(ts * freq, &s, &c);
    __half2 tp = __floats2half2_rn(s, c);
    uint32_t tu = *reinterpret_cast<uint32_t*>(&tp);

    #pragma unroll 4
    for (int t = 0; t < TT; t++) {
        float a0 = bb.x, a1 = bb.y;
        #pragma unroll
        for (int k = 0; k < AD; k++) {
            float av = sa[t*AD + k];
            a0 += av * wv[k].x;
            a1 += av * wv[k].y;
        }
        size_t row = (size_t)(b*TT + t) * K2;
        __half2 ap = __floats2half2_rn(a0, a1);
        *reinterpret_cast<uint32_t*>(&g_xf[row + j]) = *reinterpret_cast<uint32_t*>(&ap);
        *reinterpret_cast<uint32_t*>(&g_xf[row + HID + j]) = tu;
    }
}

// ---------------------------------------------------------------------------
// Grouped fp16 mma.sync GEMM, split-K x2 (blockIdx.z = K half).
// CTA: M=64 (2 samples, one cat) x N=128, K-tile 32. 8 warps, warp = 32r x 32c.
// Writes raw fp32 partials (no bias/act) to g_part[z].
// ---------------------------------------------------------------------------
#define GN    128
#define PADX  40
#define PADW  136
#define XELEM (64*PADX)          // 2560 fp16 per stage
#define WFS   (32*GN)            // 4096 fp32 per stage (512B rows, contiguous)
#define WCS   (32*PADW)          // 4352 fp16 per stage
#define OX(s)   ((s)*(XELEM*2))                 // 3 x 5120   -> [0, 15360)
#define OWF(s)  (15360 + (s)*(WFS*4))           // 2 x 16384  -> [15360, 48128)
#define OWC(s)  (48128 + (s)*(WCS*2))           // 2 x 8704   -> [48128, 65536)
#define SMEM_BYTES 65536

#define MMA_F16(d, a0,a1,a2,a3, b0,b1) \
  asm volatile("mma.sync.aligned.m16n8k16.row.col.f32.f16.f16.f32 " \
               "{%0,%1,%2,%3}, {%4,%5,%6,%7}, {%8,%9}, {%0,%1,%2,%3};" \
               : "+f"(d[0]),"+f"(d[1]),"+f"(d[2]),"+f"(d[3]) \
               : "r"(a0),"r"(a1),"r"(a2),"r"(a3),"r"(b0),"r"(b1))

#define LDSM_X4(r0,r1,r2,r3, addr) \
  asm volatile("ldmatrix.sync.aligned.m8n8.x4.shared.b16 {%0,%1,%2,%3}, [%4];" \
               : "=r"(r0),"=r"(r1),"=r"(r2),"=r"(r3) : "r"(addr))

#define LDSM_X2T(r0,r1, addr) \
  asm volatile("ldmatrix.sync.aligned.m8n8.x2.trans.shared.b16 {%0,%1}, [%2];" \
               : "=r"(r0),"=r"(r1) : "r"(addr))

#define CP16(sa, ga, sz) \
  asm volatile("cp.async.ca.shared.global [%0], [%1], 16, %2;" \
               :: "r"(sa), "l"(ga), "r"(sz))
#define CP16F(sa, ga) \
  asm volatile("cp.async.ca.shared.global [%0], [%1], 16;" :: "r"(sa), "l"(ga))
#define CP_COMMIT() asm volatile("cp.async.commit_group;" ::: "memory")

__global__ __launch_bounds__(256,3) void gemm_grouped(
    const __half* __restrict__ Xf,
    const float* __restrict__ W,
    float* __restrict__ Part,    // [2][BB*TT][HID] partials
    int K)
{
    if ((int)blockIdx.y >= g_ngroups) return;

    extern __shared__ char smem[];
    uint32_t sb;
    asm("{ .reg .u64 t; cvta.to.shared.u64 t, %1; cvt.u32.u64 %0, t; }"
        : "=r"(sb) : "l"(smem));

    int slot = blockIdx.y;
    int cat  = g_gcat[slot];
    int s0 = g_gsamp[slot][0];
    int s1 = g_gsamp[slot][1];

    int n0 = blockIdx.x * GN;
    int kbase = blockIdx.z * (K >> 1);
    int klen  = K >> 1;

    int tid  = threadIdx.x;
    int lane = tid & 31;
    int warp = tid >> 5;
    int mrow = warp & 1;
    int ncol = warp >> 1;

    int lr15 = lane & 15;
    int hiK8 = ((lane >> 4) & 1) * 8;
    int mysamp = mrow ? s1 : s0;
    bool active = (mysamp >= 0);

    float acc[2][4][4];
    #pragma unroll
    for (int mt = 0; mt < 2; mt++)
        #pragma unroll
        for (int nt = 0; nt < 4; nt++)
            #pragma unroll
            for (int j = 0; j < 4; j++) acc[mt][nt][j] = 0.0f;

    // ---- staging geometry (fully coalesced) ----
    int xrl = tid >> 2;
    int xsp = (xrl < 32) ? s0 : s1;
    uint32_t xsz = (xsp >= 0) ? 16 : 0;
    const __half* xg = Xf
        + (size_t)((xsp >= 0) ? (xsp*32 + (xrl & 31)) : 0) * K
        + kbase + (tid & 3) * 8;
    uint32_t xso = (uint32_t)(xrl*(PADX*2) + (tid & 3)*16);

    const float* wg = W + (size_t)cat * K * HID
        + (size_t)(kbase + warp) * HID + n0 + lane*4;
    const size_t wrstep = (size_t)8 * HID;
    const size_t wstep  = (size_t)32 * HID;
    uint32_t wfo = (uint32_t)(warp*512 + lane*16);
    uint32_t wco = (uint32_t)(warp*(PADW*2) + lane*8);

    int NT = klen >> 5;

    // ---- prologue: issue tiles 0 and 1 ----
    #pragma unroll
    for (int pi = 0; pi < 2; pi++) {
        CP16(sb + OX(pi) + xso, xg + pi*32, xsz);
        #pragma unroll
        for (int c = 0; c < 4; c++)
            CP16F(sb + OWF(pi) + wfo + c*4096, wg + pi*wstep + c*wrstep);
        CP_COMMIT();
    }

    #pragma unroll 1
    for (int it = 0; it < NT; it++) {
        int xs = it % 3;
        int cs = it & 1;

        if (it < NT - 1)
            asm volatile("cp.async.wait_group 1;" ::: "memory");
        else
            asm volatile("cp.async.wait_group 0;" ::: "memory");

        // convert own W chunks (tile it): 4 x (LDS.128 fp32 -> STS.64 fp16)
        #pragma unroll
        for (int c = 0; c < 4; c++) {
            float4 v = *reinterpret_cast<const float4*>(smem + OWF(cs) + wfo + c*4096);
            __half2 h0 = __floats2half2_rn(v.x, v.y);
            __half2 h1 = __floats2half2_rn(v.z, v.w);
            asm volatile("st.shared.v2.b32 [%0], {%1,%2};"
                         :: "r"(sb + OWC(cs) + wco + c*(8*PADW*2)),
                            "r"(*reinterpret_cast<uint32_t*>(&h0)),
                            "r"(*reinterpret_cast<uint32_t*>(&h1)) : "memory");
        }
        __syncthreads();

        // prefetch tile it+2
        if (it + 2 < NT) {
            int k0 = (it + 2) << 5;
            CP16(sb + OX((it + 2) % 3) + xso, xg + k0, xsz);
            const float* wsrc = wg + (size_t)(it + 2) * wstep;
            #pragma unroll
            for (int c = 0; c < 4; c++)
                CP16F(sb + OWF(cs) + wfo + c*4096, wsrc + c*wrstep);
            CP_COMMIT();
        }

        // compute tile it: warp 32x32, 2 k16 steps
        if (active) {
            #pragma unroll
            for (int ks = 0; ks < 2; ks++) {
                uint32_t a[2][4];
                #pragma unroll
                for (int mt = 0; mt < 2; mt++) {
                    uint32_t aoff = (uint32_t)(OX(xs)
                        + ((mrow*32 + mt*16 + lr15)*PADX + ks*16 + hiK8) * 2);
                    LDSM_X4(a[mt][0],a[mt][1],a[mt][2],a[mt][3], sb + aoff);
                }
                #pragma unroll
                for (int nt = 0; nt < 4; nt++) {
                    uint32_t boff = (uint32_t)(OWC(cs)
                        + ((ks*16 + lr15)*PADW + ncol*32 + nt*8) * 2);
                    uint32_t b0, b1;
                    LDSM_X2T(b0, b1, sb + boff);
                    #pragma unroll
                    for (int mt = 0; mt < 2; mt++)
                        MMA_F16(acc[mt][nt], a[mt][0],a[mt][1],a[mt][2],a[mt][3], b0,b1);
                }
            }
        }
    }

    // ---- epilogue: raw fp32 partials ----
    if (!active) return;
    float* pout = Part + (size_t)blockIdx.z * (BB*TT*HID);
    int r  = lane >> 2;
    int c2 = (lane & 3) * 2;
    #pragma unroll
    for (int mt = 0; mt < 2; mt++) {
        int grow0 = mysamp*32 + mt*16 + r;
        #pragma unroll
        for (int nt = 0; nt < 4; nt++) {
            int col = n0 + ncol*32 + nt*8 + c2;
            float2 o01 = {acc[mt][nt][0], acc[mt][nt][1]};
            float2 o23 = {acc[mt][nt][2], acc[mt][nt][3]};
            *reinterpret_cast<float2*>(&pout[(size_t)grow0*HID + col]) = o01;
            *reinterpret_cast<float2*>(&pout[(size_t)(grow0+8)*HID + col]) = o23;
        }
    }
}

// ---------------------------------------------------------------------------
// Reduce: out = act(part0 + part1 + bias[cat]).  writeH: swish -> fp16 g_hf,
// else fp32 -> Yf32.
// ---------------------------------------------------------------------------
__global__ __launch_bounds__(256) void reduce_bias_act(
    const float* __restrict__ part,
    const float* __restrict__ bias,
    const int*   __restrict__ cats,
    float* __restrict__ Yf32,
    int writeH)
{
    int idx = blockIdx.x * 256 + threadIdx.x;   // float4 index
    int e0  = idx * 4;
    int row = e0 / HID;
    int col = e0 - row * HID;
    int cat = cats[row >> 5];

    float4 p0 = reinterpret_cast<const float4*>(part)[idx];
    float4 p1 = reinterpret_cast<const float4*>(part + (size_t)BB*TT*HID)[idx];
    float4 bv = *reinterpret_cast<const float4*>(&bias[(size_t)cat*HID + col]);
    float y0 = p0.x + p1.x + bv.x;
    float y1 = p0.y + p1.y + bv.y;
    float y2 = p0.z + p1.z + bv.z;
    float y3 = p0.w + p1.w + bv.w;

    if (writeH) {
        y0 = y0 / (1.0f + __expf(-y0));
        y1 = y1 / (1.0f + __expf(-y1));
        y2 = y2 / (1.0f + __expf(-y2));
        y3 = y3 / (1.0f + __expf(-y3));
        __half2 h01 = __floats2half2_rn(y0, y1);
        __half2 h23 = __floats2half2_rn(y2, y3);
        uint2 u = { *reinterpret_cast<uint32_t*>(&h01),
                    *reinterpret_cast<uint32_t*>(&h23) };
        *reinterpret_cast<uint2*>(&g_hf[e0]) = u;
    } else {
        float4 o = {y0, y1, y2, y3};
        reinterpret_cast<float4*>(Yf32)[idx] = o;
    }
}

// ---------------------------------------------------------------------------
extern "C" void kernel_launch(void* const* d_in, const int* in_sizes, int n_in,
                              void* d_out, int out_size)
{
    const float* actions   = (const float*)d_in[0];
    const int*   timesteps = (const int*)  d_in[1];
    const int*   cat_ids   = (const int*)  d_in[2];
    const float* W1        = (const float*)d_in[3];
    const float* b1        = (const float*)d_in[4];
    const float* W2        = (const float*)d_in[5];
    const float* b2        = (const float*)d_in[6];
    const float* W3        = (const float*)d_in[7];
    const float* b3        = (const float*)d_in[8];
    float* out = (float*)d_out;

    __half *xf, *hf;
    float *part;
    cudaGetSymbolAddress((void**)&xf, g_xf);
    cudaGetSymbolAddress((void**)&hf, g_hf);
    cudaGetSymbolAddress((void**)&part, g_part);

    static bool attr_set = false;
    if (!attr_set) {
        cudaFuncSetAttribute(gemm_grouped,
                             cudaFuncAttributeMaxDynamicSharedMemorySize, SMEM_BYTES);
        attr_set = true;
    }

    const int RED_GRID = (BB*TT*HID) / (4*256);   // 1536

    setup_groups<<<1, 32>>>(cat_ids);
    embed_kernel<<<dim3(BB, 3), 256>>>(actions, timesteps, cat_ids, W1, b1);

    // h = swish(x @ W2[cat] + b2) -> fp16  (split-K2 + reduce)
    gemm_grouped<<<dim3(HID/GN, 32, 2), 256, SMEM_BYTES>>>(xf, W2, part, K2);
    reduce_bias_act<<<RED_GRID, 256>>>(part, b2, cat_ids, nullptr, 1);

    // out = h @ W3[cat] + b3 -> fp32  (split-K2 + reduce)
    gemm_grouped<<<dim3(HID/GN, 32, 2), 256, SMEM_BYTES>>>(hf, W3, part, HID);
    reduce_bias_act<<<RED_GRID, 256>>>(part, b3, cat_ids, out, 0);
}

// round 14
// speedup vs baseline: 1.0295x; 1.0295x over previous
#include <cuda_runtime.h>
#include <cuda_fp16.h>
#include <math.h>
#include <stdint.h>

// Problem constants
#define BB 32
#define TT 32
#define AD 32
#define HID 1536
#define K2 (2*HID)   // 3072

// Scratch (__device__ globals)
__device__ __half g_xf[BB*TT*K2];    // concat([a_emb, tau]) fp16
__device__ __half g_hf[BB*TT*HID];   // swish hidden fp16
__device__ int g_gcat[32];
__device__ int g_gsamp[32][2];
__device__ int g_ngroups;

// ---------------------------------------------------------------------------
// Kernel 1: x = [actions @ W1[cat] + b1, sinusoidal(ts)] -> fp16.
// Block (0,0) warp 0 additionally computes the cat grouping (pairs).
// ---------------------------------------------------------------------------
__global__ __launch_bounds__(256) void embed_kernel(
    const float* __restrict__ actions,
    const int*   __restrict__ timesteps,
    const int*   __restrict__ cats,
    const float* __restrict__ W1,
    const float* __restrict__ b1)
{
    int b = blockIdx.x;

    // ---- grouping (one warp of one block) ----
    if (b == 0 && blockIdx.y == 0 && threadIdx.x < 32) {
        int t = threadIdx.x;
        int myc = cats[t];
        unsigned mask = 0;
        #pragma unroll
        for (int s = 0; s < 32; s++) {
            int cs = __shfl_sync(0xffffffffu, myc, s);
            if (cs == t) mask |= (1u << s);
        }
        int cnt = __popc(mask);
        int ng  = (cnt + 1) >> 1;
        int incl = ng;
        #pragma unroll
        for (int off = 1; off < 32; off <<= 1) {
            int v = __shfl_up_sync(0xffffffffu, incl, off);
            if (t >= off) incl += v;
        }
        int pre   = incl - ng;
        int total = __shfl_sync(0xffffffffu, incl, 31);
        if (t == 0) g_ngroups = total;
        unsigned m = mask;
        for (int g = 0; g < ng; g++) {
            int slot = pre + g;
            g_gcat[slot] = t;
            #pragma unroll
            for (int j = 0; j < 2; j++) {
                int s = -1;
                if (m) { s = __ffs(m) - 1; m &= m - 1; }
                g_gsamp[slot][j] = s;
            }
        }
        for (int slot = total + t; slot < 32; slot += 32) {
            g_gcat[slot] = -1;
            g_gsamp[slot][0] = -1;
            g_gsamp[slot][1] = -1;
        }
    }

    int p = blockIdx.y * 256 + threadIdx.x;
    int j = 2 * p;

    __shared__ float sa[TT*AD];
    for (int i = threadIdx.x; i < TT*AD; i += 256)
        sa[i] = actions[(size_t)b*TT*AD + i];
    __syncthreads();

    int cat = cats[b];
    const float* Wc = W1 + (size_t)cat * AD * HID;
    float2 bb = *reinterpret_cast<const float2*>(&b1[(size_t)cat*HID + j]);

    float2 wv[AD];
    #pragma unroll
    for (int k = 0; k < AD; k++)
        wv[k] = *reinterpret_cast<const float2*>(&Wc[(size_t)k*HID + j]);

    const float C = -9.210340371976184f / 768.0f;
    float ts = (float)timesteps[b];
    float freq = expf(C * (float)p);
    float s, c;
    sincosf(ts * freq, &s, &c);
    __half2 tp = __floats2half2_rn(s, c);
    uint32_t tu = *reinterpret_cast<uint32_t*>(&tp);

    #pragma unroll 4
    for (int t = 0; t < TT; t++) {
        float a0 = bb.x, a1 = bb.y;
        #pragma unroll
        for (int k = 0; k < AD; k++) {
            float av = sa[t*AD + k];
            a0 += av * wv[k].x;
            a1 += av * wv[k].y;
        }
        size_t row = (size_t)(b*TT + t) * K2;
        __half2 ap = __floats2half2_rn(a0, a1);
        *reinterpret_cast<uint32_t*>(&g_xf[row + j]) = *reinterpret_cast<uint32_t*>(&ap);
        *reinterpret_cast<uint32_t*>(&g_xf[row + HID + j]) = tu;
    }
}

// ---------------------------------------------------------------------------
// Grouped fp16 mma.sync GEMM, convert-off-critical-path pipeline.
// CTA: M=64 (2 samples, one cat) x N=128, K-tile 32. 8 warps, warp = 32r x 32c.
// Separate cp.async commit groups for W and X (W committed first):
//   iter it: wait_group 1  -> W(it+1), X(it) arrived (X(it+1) may fly)
//            __syncthreads -> prev region done (convert(it) visible)
//            issue W(it+2), X(it+2)
//            convert(it+1)  ||  compute(it)      (independent work)
// ---------------------------------------------------------------------------
#define GN    128
#define PADX  40
#define PADW  136
#define XELEM (64*PADX)          // 2560 fp16 per stage
#define WFS   (32*GN)            // 4096 fp32 per stage (512B rows, contiguous)
#define WCS   (32*PADW)          // 4352 fp16 per stage
#define OX(s)   ((s)*(XELEM*2))                 // 3 x 5120   -> [0, 15360)
#define OWF(s)  (15360 + (s)*(WFS*4))           // 2 x 16384  -> [15360, 48128)
#define OWC(s)  (48128 + (s)*(WCS*2))           // 2 x 8704   -> [48128, 65536)
#define SMEM_BYTES 65536

#define MMA_F16(d, a0,a1,a2,a3, b0,b1) \
  asm volatile("mma.sync.aligned.m16n8k16.row.col.f32.f16.f16.f32 " \
               "{%0,%1,%2,%3}, {%4,%5,%6,%7}, {%8,%9}, {%0,%1,%2,%3};" \
               : "+f"(d[0]),"+f"(d[1]),"+f"(d[2]),"+f"(d[3]) \
               : "r"(a0),"r"(a1),"r"(a2),"r"(a3),"r"(b0),"r"(b1))

#define LDSM_X4(r0,r1,r2,r3, addr) \
  asm volatile("ldmatrix.sync.aligned.m8n8.x4.shared.b16 {%0,%1,%2,%3}, [%4];" \
               : "=r"(r0),"=r"(r1),"=r"(r2),"=r"(r3) : "r"(addr))

#define LDSM_X2T(r0,r1, addr) \
  asm volatile("ldmatrix.sync.aligned.m8n8.x2.trans.shared.b16 {%0,%1}, [%2];" \
               : "=r"(r0),"=r"(r1) : "r"(addr))

#define CP16(sa, ga, sz) \
  asm volatile("cp.async.ca.shared.global [%0], [%1], 16, %2;" \
               :: "r"(sa), "l"(ga), "r"(sz))
#define CP16F(sa, ga) \
  asm volatile("cp.async.ca.shared.global [%0], [%1], 16;" :: "r"(sa), "l"(ga))
#define CP_COMMIT() asm volatile("cp.async.commit_group;" ::: "memory")

__global__ __launch_bounds__(256,3) void gemm_grouped(
    const __half* __restrict__ Xf,
    const float* __restrict__ W,
    const float* __restrict__ bias,
    float* __restrict__ Yf32,
    int K, int writeH)
{
    if ((int)blockIdx.y >= g_ngroups) return;

    extern __shared__ char smem[];
    uint32_t sb;
    asm("{ .reg .u64 t; cvta.to.shared.u64 t, %1; cvt.u32.u64 %0, t; }"
        : "=r"(sb) : "l"(smem));

    int slot = blockIdx.y;
    int cat  = g_gcat[slot];
    int s0 = g_gsamp[slot][0];
    int s1 = g_gsamp[slot][1];

    int n0 = blockIdx.x * GN;

    int tid  = threadIdx.x;
    int lane = tid & 31;
    int warp = tid >> 5;
    int mrow = warp & 1;
    int ncol = warp >> 1;

    int lr15 = lane & 15;
    int hiK8 = ((lane >> 4) & 1) * 8;
    int mysamp = mrow ? s1 : s0;
    bool active = (mysamp >= 0);

    float acc[2][4][4];
    #pragma unroll
    for (int mt = 0; mt < 2; mt++)
        #pragma unroll
        for (int nt = 0; nt < 4; nt++)
            #pragma unroll
            for (int j = 0; j < 4; j++) acc[mt][nt][j] = 0.0f;

    // X: 64 rows x 32 k fp16 = 256 x 16B chunks, 1/thread
    int xrl = tid >> 2;
    int xsp = (xrl < 32) ? s0 : s1;
    uint32_t xsz = (xsp >= 0) ? 16 : 0;
    const __half* xg = Xf
        + (size_t)((xsp >= 0) ? (xsp*32 + (xrl & 31)) : 0) * K + (tid & 3) * 8;
    uint32_t xso = (uint32_t)(xrl*(PADX*2) + (tid & 3)*16);

    // W fp32: 32 k x 128 n, 4 chunks/thread; chunk c: row = c*8+warp, col = lane
    const float* wg = W + (size_t)cat * K * HID + (size_t)warp * HID + n0 + lane*4;
    const size_t wrstep = (size_t)8 * HID;
    const size_t wstep  = (size_t)32 * HID;
    uint32_t wfo = (uint32_t)(warp*512 + lane*16);
    uint32_t wco = (uint32_t)(warp*(PADW*2) + lane*8);

    int NT = K >> 5;

    // ---- prologue: commit W0,X0,W1,X1 (4 groups, W before X) ----
    #pragma unroll
    for (int pi = 0; pi < 2; pi++) {
        #pragma unroll
        for (int c = 0; c < 4; c++)
            CP16F(sb + OWF(pi) + wfo + c*4096, wg + pi*wstep + c*wrstep);
        CP_COMMIT();
        CP16(sb + OX(pi) + xso, xg + pi*32, xsz);
        CP_COMMIT();
    }
    // W0, X0 arrived (leave W1, X1 in flight); convert tile 0
    asm volatile("cp.async.wait_group 2;" ::: "memory");
    #pragma unroll
    for (int c = 0; c < 4; c++) {
        float4 v = *reinterpret_cast<const float4*>(smem + OWF(0) + wfo + c*4096);
        __half2 h0 = __floats2half2_rn(v.x, v.y);
        __half2 h1 = __floats2half2_rn(v.z, v.w);
        asm volatile("st.shared.v2.b32 [%0], {%1,%2};"
                     :: "r"(sb + OWC(0) + wco + c*(8*PADW*2)),
                        "r"(*reinterpret_cast<uint32_t*>(&h0)),
                        "r"(*reinterpret_cast<uint32_t*>(&h1)) : "memory");
    }

    #pragma unroll 1
    for (int it = 0; it < NT; it++) {
        int xs = it % 3;
        int cs = it & 1;

        // ensure W(it+1) and X(it) arrived (X(it+1) may still fly)
        if (it < NT - 1)
            asm volatile("cp.async.wait_group 1;" ::: "memory");
        else
            asm volatile("cp.async.wait_group 0;" ::: "memory");

        __syncthreads();   // prev region done: convert(it) visible; WF(it&1) free

        // issue tile it+2 (W group, then X group)
        if (it + 2 < NT) {
            int k0 = (it + 2) << 5;
            const float* wsrc = wg + (size_t)(it + 2) * wstep;
            #pragma unroll
            for (int c = 0; c < 4; c++)
                CP16F(sb + OWF(cs) + wfo + c*4096, wsrc + c*wrstep);
            CP_COMMIT();
            CP16(sb + OX((it + 2) % 3) + xso, xg + k0, xsz);
            CP_COMMIT();
        }

        // convert tile it+1 (independent of compute below)
        if (it + 1 < NT) {
            int nc = (it + 1) & 1;
            #pragma unroll
            for (int c = 0; c < 4; c++) {
                float4 v = *reinterpret_cast<const float4*>(smem + OWF(nc) + wfo + c*4096);
                __half2 h0 = __floats2half2_rn(v.x, v.y);
                __half2 h1 = __floats2half2_rn(v.z, v.w);
                asm volatile("st.shared.v2.b32 [%0], {%1,%2};"
                             :: "r"(sb + OWC(nc) + wco + c*(8*PADW*2)),
                                "r"(*reinterpret_cast<uint32_t*>(&h0)),
                                "r"(*reinterpret_cast<uint32_t*>(&h1)) : "memory");
            }
        }

        // compute tile it (WC(it&1) converted in prev region, OX(it%3) arrived)
        if (active) {
            #pragma unroll
            for (int ks = 0; ks < 2; ks++) {
                uint32_t a[2][4];
                #pragma unroll
                for (int mt = 0; mt < 2; mt++) {
                    uint32_t aoff = (uint32_t)(OX(xs)
                        + ((mrow*32 + mt*16 + lr15)*PADX + ks*16 + hiK8) * 2);
                    LDSM_X4(a[mt][0],a[mt][1],a[mt][2],a[mt][3], sb + aoff);
                }
                #pragma unroll
                for (int nt = 0; nt < 4; nt++) {
                    uint32_t boff = (uint32_t)(OWC(cs)
                        + ((ks*16 + lr15)*PADW + ncol*32 + nt*8) * 2);
                    uint32_t b0, b1;
                    LDSM_X2T(b0, b1, sb + boff);
                    #pragma unroll
                    for (int mt = 0; mt < 2; mt++)
                        MMA_F16(acc[mt][nt], a[mt][0],a[mt][1],a[mt][2],a[mt][3], b0,b1);
                }
            }
        }
    }

    // ---- epilogue ----
    if (!active) return;
    int r  = lane >> 2;
    int c2 = (lane & 3) * 2;
    #pragma unroll
    for (int mt = 0; mt < 2; mt++) {
        int grow0 = mysamp*32 + mt*16 + r;
        #pragma unroll
        for (int nt = 0; nt < 4; nt++) {
            int col = n0 + ncol*32 + nt*8 + c2;
            float2 bv = *reinterpret_cast<const float2*>(&bias[(size_t)cat*HID + col]);
            float y0 = acc[mt][nt][0] + bv.x;
            float y1 = acc[mt][nt][1] + bv.y;
            float y2 = acc[mt][nt][2] + bv.x;
            float y3 = acc[mt][nt][3] + bv.y;
            if (writeH) {
                y0 = y0 / (1.0f + __expf(-y0));
                y1 = y1 / (1.0f + __expf(-y1));
                y2 = y2 / (1.0f + __expf(-y2));
                y3 = y3 / (1.0f + __expf(-y3));
                __half2 p01 = __floats2half2_rn(y0, y1);
                __half2 p23 = __floats2half2_rn(y2, y3);
                *reinterpret_cast<uint32_t*>(&g_hf[(size_t)grow0*HID + col])
                    = *reinterpret_cast<uint32_t*>(&p01);
                *reinterpret_cast<uint32_t*>(&g_hf[(size_t)(grow0+8)*HID + col])
                    = *reinterpret_cast<uint32_t*>(&p23);
            } else {
                float2 o01 = {y0, y1};
                float2 o23 = {y2, y3};
                *reinterpret_cast<float2*>(&Yf32[(size_t)grow0*HID + col]) = o01;
                *reinterpret_cast<float2*>(&Yf32[(size_t)(grow0+8)*HID + col]) = o23;
            }
        }
    }
}

// ---------------------------------------------------------------------------
extern "C" void kernel_launch(void* const* d_in, const int* in_sizes, int n_in,
                              void* d_out, int out_size)
{
    const float* actions   = (const float*)d_in[0];
    const int*   timesteps = (const int*)  d_in[1];
    const int*   cat_ids   = (const int*)  d_in[2];
    const float* W1        = (const float*)d_in[3];
    const float* b1        = (const float*)d_in[4];
    const float* W2        = (const float*)d_in[5];
    const float* b2        = (const float*)d_in[6];
    const float* W3        = (const float*)d_in[7];
    const float* b3        = (const float*)d_in[8];
    float* out = (float*)d_out;

    __half *xf, *hf;
    cudaGetSymbolAddress((void**)&xf, g_xf);
    cudaGetSymbolAddress((void**)&hf, g_hf);

    static bool attr_set = false;
    if (!attr_set) {
        cudaFuncSetAttribute(gemm_grouped,
                             cudaFuncAttributeMaxDynamicSharedMemorySize, SMEM_BYTES);
        attr_set = true;
    }

    // embed also computes grouping (block (0,0), warp 0)
    embed_kernel<<<dim3(BB, 3), 256>>>(actions, timesteps, cat_ids, W1, b1);

    // h = swish(x @ W2[cat] + b2) -> fp16
    gemm_grouped<<<dim3(HID/GN, 32), 256, SMEM_BYTES>>>(xf, W2, b2, nullptr, K2, 1);

    // out = h @ W3[cat] + b3 -> fp32
    gemm_grouped<<<dim3(HID/GN, 32), 256, SMEM_BYTES>>>(hf, W3, b3, out, HID, 0);
}

// round 15
// speedup vs baseline: 1.0388x; 1.0090x over previous
#include <cuda_runtime.h>
#include <cuda_fp16.h>
#include <math.h>
#include <stdint.h>

// Problem constants
#define BB 32
#define TT 32
#define AD 32
#define HID 1536
#define K2 (2*HID)   // 3072

// Scratch (__device__ globals)
__device__ __half g_xf[BB*TT*K2];    // concat([a_emb, tau]) fp16
__device__ __half g_hf[BB*TT*HID];   // swish hidden fp16
__device__ int g_gcat[32];
__device__ int g_gsamp[32][2];
__device__ int g_ngroups;

// ---------------------------------------------------------------------------
// Setup: group samples by cat in pairs. One warp.
// ---------------------------------------------------------------------------
__global__ void setup_groups(const int* __restrict__ cats)
{
    int t = threadIdx.x;
    int myc = cats[t];
    unsigned mask = 0;
    #pragma unroll
    for (int s = 0; s < 32; s++) {
        int cs = __shfl_sync(0xffffffffu, myc, s);
        if (cs == t) mask |= (1u << s);
    }
    int cnt = __popc(mask);
    int ng  = (cnt + 1) >> 1;

    int incl = ng;
    #pragma unroll
    for (int off = 1; off < 32; off <<= 1) {
        int v = __shfl_up_sync(0xffffffffu, incl, off);
        if (t >= off) incl += v;
    }
    int pre   = incl - ng;
    int total = __shfl_sync(0xffffffffu, incl, 31);
    if (t == 0) g_ngroups = total;

    unsigned m = mask;
    for (int g = 0; g < ng; g++) {
        int slot = pre + g;
        g_gcat[slot] = t;
        #pragma unroll
        for (int j = 0; j < 2; j++) {
            int s = -1;
            if (m) { s = __ffs(m) - 1; m &= m - 1; }
            g_gsamp[slot][j] = s;
        }
    }
    for (int slot = total + t; slot < 32; slot += 32) {
        g_gcat[slot] = -1;
        g_gsamp[slot][0] = -1;
        g_gsamp[slot][1] = -1;
    }
}

// ---------------------------------------------------------------------------
// Kernel 1: x = [actions @ W1[cat] + b1, sinusoidal(ts)] -> fp16
// ---------------------------------------------------------------------------
__global__ __launch_bounds__(256) void embed_kernel(
    const float* __restrict__ actions,
    const int*   __restrict__ timesteps,
    const int*   __restrict__ cats,
    const float* __restrict__ W1,
    const float* __restrict__ b1)
{
    int b = blockIdx.x;
    int p = blockIdx.y * 256 + threadIdx.x;
    int j = 2 * p;

    __shared__ float sa[TT*AD];
    for (int i = threadIdx.x; i < TT*AD; i += 256)
        sa[i] = actions[(size_t)b*TT*AD + i];
    __syncthreads();

    int cat = cats[b];
    const float* Wc = W1 + (size_t)cat * AD * HID;
    float2 bb = *reinterpret_cast<const float2*>(&b1[(size_t)cat*HID + j]);

    float2 wv[AD];
    #pragma unroll
    for (int k = 0; k < AD; k++)
        wv[k] = *reinterpret_cast<const float2*>(&Wc[(size_t)k*HID + j]);

    const float C = -9.210340371976184f / 768.0f;
    float ts = (float)timesteps[b];
    float freq = expf(C * (float)p);
    float s, c;
    sincosf(ts * freq, &s, &c);
    __half2 tp = __floats2half2_rn(s, c);
    uint32_t tu = *reinterpret_cast<uint32_t*>(&tp);

    #pragma unroll 4
    for (int t = 0; t < TT; t++) {
        float a0 = bb.x, a1 = bb.y;
        #pragma unroll
        for (int k = 0; k < AD; k++) {
            float av = sa[t*AD + k];
            a0 += av * wv[k].x;
            a1 += av * wv[k].y;
        }
        size_t row = (size_t)(b*TT + t) * K2;
        __half2 ap = __floats2half2_rn(a0, a1);
        *reinterpret_cast<uint32_t*>(&g_xf[row + j]) = *reinterpret_cast<uint32_t*>(&ap);
        *reinterpret_cast<uint32_t*>(&g_xf[row + HID + j]) = tu;
    }
}

// ---------------------------------------------------------------------------
// Grouped fp16 mma.sync GEMM, prefetch-distance-3 pipeline.
// CTA: M=64 (2 samples, one cat) x N=128, K-tile 32. 8 warps, warp = 32r x 32c.
// One combined {W,X} cp.async group per tile; rings X x4, WF x3, WC x2.
// iter it: wait_group 1 (group it+1 arrived; it+2 may fly); sync;
//          issue it+3; convert(it+1) || compute(it).
// ---------------------------------------------------------------------------
#define GN    128
#define PADX  40
#define PADW  136
#define XELEM (64*PADX)          // 2560 fp16 per X stage (5120 B)
#define OX(s)   ((s)*5120)                      // 4 x 5120   -> [0, 20480)
#define OWF(s)  (20480 + (s)*16384)             // 3 x 16384  -> [20480, 69632)
#define OWC(s)  (69632 + (s)*8704)              // 2 x 8704   -> [69632, 87040)
#define SMEM_BYTES 87040

#define MMA_F16(d, a0,a1,a2,a3, b0,b1) \
  asm volatile("mma.sync.aligned.m16n8k16.row.col.f32.f16.f16.f32 " \
               "{%0,%1,%2,%3}, {%4,%5,%6,%7}, {%8,%9}, {%0,%1,%2,%3};" \
               : "+f"(d[0]),"+f"(d[1]),"+f"(d[2]),"+f"(d[3]) \
               : "r"(a0),"r"(a1),"r"(a2),"r"(a3),"r"(b0),"r"(b1))

#define LDSM_X4(r0,r1,r2,r3, addr) \
  asm volatile("ldmatrix.sync.aligned.m8n8.x4.shared.b16 {%0,%1,%2,%3}, [%4];" \
               : "=r"(r0),"=r"(r1),"=r"(r2),"=r"(r3) : "r"(addr))

#define LDSM_X2T(r0,r1, addr) \
  asm volatile("ldmatrix.sync.aligned.m8n8.x2.trans.shared.b16 {%0,%1}, [%2];" \
               : "=r"(r0),"=r"(r1) : "r"(addr))

#define CP16(sa, ga, sz) \
  asm volatile("cp.async.ca.shared.global [%0], [%1], 16, %2;" \
               :: "r"(sa), "l"(ga), "r"(sz))
#define CP16F(sa, ga) \
  asm volatile("cp.async.ca.shared.global [%0], [%1], 16;" :: "r"(sa), "l"(ga))
#define CP_COMMIT() asm volatile("cp.async.commit_group;" ::: "memory")

__global__ __launch_bounds__(256,2) void gemm_grouped(
    const __half* __restrict__ Xf,
    const float* __restrict__ W,
    const float* __restrict__ bias,
    float* __restrict__ Yf32,
    int K, int writeH)
{
    if ((int)blockIdx.y >= g_ngroups) return;

    extern __shared__ char smem[];
    uint32_t sb;
    asm("{ .reg .u64 t; cvta.to.shared.u64 t, %1; cvt.u32.u64 %0, t; }"
        : "=r"(sb) : "l"(smem));

    int slot = blockIdx.y;
    int cat  = g_gcat[slot];
    int s0 = g_gsamp[slot][0];
    int s1 = g_gsamp[slot][1];

    int n0 = blockIdx.x * GN;

    int tid  = threadIdx.x;
    int lane = tid & 31;
    int warp = tid >> 5;
    int mrow = warp & 1;
    int ncol = warp >> 1;

    int lr15 = lane & 15;
    int hiK8 = ((lane >> 4) & 1) * 8;
    int mysamp = mrow ? s1 : s0;
    bool active = (mysamp >= 0);

    float acc[2][4][4];
    #pragma unroll
    for (int mt = 0; mt < 2; mt++)
        #pragma unroll
        for (int nt = 0; nt < 4; nt++)
            #pragma unroll
            for (int j = 0; j < 4; j++) acc[mt][nt][j] = 0.0f;

    // X: 64 rows x 32 k fp16 = 256 x 16B chunks, 1/thread
    int xrl = tid >> 2;
    int xsp = (xrl < 32) ? s0 : s1;
    uint32_t xsz = (xsp >= 0) ? 16 : 0;
    const __half* xg = Xf
        + (size_t)((xsp >= 0) ? (xsp*32 + (xrl & 31)) : 0) * K + (tid & 3) * 8;
    uint32_t xso = (uint32_t)(xrl*(PADX*2) + (tid & 3)*16);

    // W fp32: 32 k x 128 n, 4 chunks/thread; chunk c: row = c*8+warp, col = lane
    const float* wg = W + (size_t)cat * K * HID + (size_t)warp * HID + n0 + lane*4;
    const size_t wrstep = (size_t)8 * HID;
    const size_t wstep  = (size_t)32 * HID;
    uint32_t wfo = (uint32_t)(warp*512 + lane*16);
    uint32_t wco = (uint32_t)(warp*(PADW*2) + lane*8);

    int NT = K >> 5;   // 96 or 48 (>= 3 always)

    // ---- prologue: commit tiles 0,1,2 ----
    #pragma unroll
    for (int pi = 0; pi < 3; pi++) {
        #pragma unroll
        for (int c = 0; c < 4; c++)
            CP16F(sb + OWF(pi) + wfo + c*4096, wg + pi*wstep + c*wrstep);
        CP16(sb + OX(pi) + xso, xg + pi*32, xsz);
        CP_COMMIT();
    }
    // tile 0 arrived (1,2 may fly); convert tile 0 -> WC0
    asm volatile("cp.async.wait_group 2;" ::: "memory");
    #pragma unroll
    for (int c = 0; c < 4; c++) {
        float4 v = *reinterpret_cast<const float4*>(smem + OWF(0) + wfo + c*4096);
        __half2 h0 = __floats2half2_rn(v.x, v.y);
        __half2 h1 = __floats2half2_rn(v.z, v.w);
        asm volatile("st.shared.v2.b32 [%0], {%1,%2};"
                     :: "r"(sb + OWC(0) + wco + c*(8*PADW*2)),
                        "r"(*reinterpret_cast<uint32_t*>(&h0)),
                        "r"(*reinterpret_cast<uint32_t*>(&h1)) : "memory");
    }

    #pragma unroll 1
    for (int it = 0; it < NT; it++) {
        int xs = it & 3;
        int cs = it & 1;

        // group(it+1) arrived; group(it+2) may still fly
        if (it + 2 < NT)
            asm volatile("cp.async.wait_group 1;" ::: "memory");
        else
            asm volatile("cp.async.wait_group 0;" ::: "memory");

        __syncthreads();   // prev region done: WC(it&1) visible; old slots free

        // issue tile it+3: WF((it+3)%3), X((it+3)&3)
        if (it + 3 < NT) {
            int tn = it + 3;
            int wfs = tn % 3;
            const float* wsrc = wg + (size_t)tn * wstep;
            #pragma unroll
            for (int c = 0; c < 4; c++)
                CP16F(sb + OWF(wfs) + wfo + c*4096, wsrc + c*wrstep);
            CP16(sb + OX(tn & 3) + xso, xg + (tn << 5), xsz);
            CP_COMMIT();
        }

        // convert tile it+1 (independent of compute below)
        if (it + 1 < NT) {
            int nf = (it + 1) % 3;
            int nc = (it + 1) & 1;
            #pragma unroll
            for (int c = 0; c < 4; c++) {
                float4 v = *reinterpret_cast<const float4*>(smem + OWF(nf) + wfo + c*4096);
                __half2 h0 = __floats2half2_rn(v.x, v.y);
                __half2 h1 = __floats2half2_rn(v.z, v.w);
                asm volatile("st.shared.v2.b32 [%0], {%1,%2};"
                             :: "r"(sb + OWC(nc) + wco + c*(8*PADW*2)),
                                "r"(*reinterpret_cast<uint32_t*>(&h0)),
                                "r"(*reinterpret_cast<uint32_t*>(&h1)) : "memory");
            }
        }

        // compute tile it: warp 32x32, 2 k16 steps
        if (active) {
            #pragma unroll
            for (int ks = 0; ks < 2; ks++) {
                uint32_t a[2][4];
                #pragma unroll
                for (int mt = 0; mt < 2; mt++) {
                    uint32_t aoff = (uint32_t)(OX(xs)
                        + ((mrow*32 + mt*16 + lr15)*PADX + ks*16 + hiK8) * 2);
                    LDSM_X4(a[mt][0],a[mt][1],a[mt][2],a[mt][3], sb + aoff);
                }
                #pragma unroll
                for (int nt = 0; nt < 4; nt++) {
                    uint32_t boff = (uint32_t)(OWC(cs)
                        + ((ks*16 + lr15)*PADW + ncol*32 + nt*8) * 2);
                    uint32_t b0, b1;
                    LDSM_X2T(b0, b1, sb + boff);
                    #pragma unroll
                    for (int mt = 0; mt < 2; mt++)
                        MMA_F16(acc[mt][nt], a[mt][0],a[mt][1],a[mt][2],a[mt][3], b0,b1);
                }
            }
        }
    }

    // ---- epilogue ----
    if (!active) return;
    int r  = lane >> 2;
    int c2 = (lane & 3) * 2;
    #pragma unroll
    for (int mt = 0; mt < 2; mt++) {
        int grow0 = mysamp*32 + mt*16 + r;
        #pragma unroll
        for (int nt = 0; nt < 4; nt++) {
            int col = n0 + ncol*32 + nt*8 + c2;
            float2 bv = *reinterpret_cast<const float2*>(&bias[(size_t)cat*HID + col]);
            float y0 = acc[mt][nt][0] + bv.x;
            float y1 = acc[mt][nt][1] + bv.y;
            float y2 = acc[mt][nt][2] + bv.x;
            float y3 = acc[mt][nt][3] + bv.y;
            if (writeH) {
                y0 = y0 / (1.0f + __expf(-y0));
                y1 = y1 / (1.0f + __expf(-y1));
                y2 = y2 / (1.0f + __expf(-y2));
                y3 = y3 / (1.0f + __expf(-y3));
                __half2 p01 = __floats2half2_rn(y0, y1);
                __half2 p23 = __floats2half2_rn(y2, y3);
                *reinterpret_cast<uint32_t*>(&g_hf[(size_t)grow0*HID + col])
                    = *reinterpret_cast<uint32_t*>(&p01);
                *reinterpret_cast<uint32_t*>(&g_hf[(size_t)(grow0+8)*HID + col])
                    = *reinterpret_cast<uint32_t*>(&p23);
            } else {
                float2 o01 = {y0, y1};
                float2 o23 = {y2, y3};
                *reinterpret_cast<float2*>(&Yf32[(size_t)grow0*HID + col]) = o01;
                *reinterpret_cast<float2*>(&Yf32[(size_t)(grow0+8)*HID + col]) = o23;
            }
        }
    }
}

// ---------------------------------------------------------------------------
extern "C" void kernel_launch(void* const* d_in, const int* in_sizes, int n_in,
                              void* d_out, int out_size)
{
    const float* actions   = (const float*)d_in[0];
    const int*   timesteps = (const int*)  d_in[1];
    const int*   cat_ids   = (const int*)  d_in[2];
    const float* W1        = (const float*)d_in[3];
    const float* b1        = (const float*)d_in[4];
    const float* W2        = (const float*)d_in[5];
    const float* b2        = (const float*)d_in[6];
    const float* W3        = (const float*)d_in[7];
    const float* b3        = (const float*)d_in[8];
    float* out = (float*)d_out;

    __half *xf, *hf;
    cudaGetSymbolAddress((void**)&xf, g_xf);
    cudaGetSymbolAddress((void**)&hf, g_hf);

    static bool attr_set = false;
    if (!attr_set) {
        cudaFuncSetAttribute(gemm_grouped,
                             cudaFuncAttributeMaxDynamicSharedMemorySize, SMEM_BYTES);
        attr_set = true;
    }

    setup_groups<<<1, 32>>>(cat_ids);
    embed_kernel<<<dim3(BB, 3), 256>>>(actions, timesteps, cat_ids, W1, b1);

    // h = swish(x @ W2[cat] + b2) -> fp16
    gemm_grouped<<<dim3(HID/GN, 32), 256, SMEM_BYTES>>>(xf, W2, b2, nullptr, K2, 1);

    // out = h @ W3[cat] + b3 -> fp32
    gemm_grouped<<<dim3(HID/GN, 32), 256, SMEM_BYTES>>>(hf, W3, b3, out, HID, 0);
}